// round 6
// baseline (speedup 1.0000x reference)
#include <cuda_runtime.h>
#include <cuda_bf16.h>
#include <math.h>
#include <stdint.h>

#define NN  100000
#define EE  1600000
#define HID 128
#define CAP 128
#define EPSB 1e-5f

// ---------------- scratch (static device globals; no allocation anywhere) ----------------
__device__ int   g_cursor[NN];                 // doubles as in-degree count
__device__ float g_dinv[NN];
__device__ int   g_esrc [(size_t)NN * CAP];
__device__ float g_bufA[(size_t)NN * HID];
__device__ float g_bufB[(size_t)NN * HID];
// layout: [0]=sum1 [128]=sq1 [256]=scale1 [384]=shift1 [512]=sum2 [640]=sq2 [768]=scale2 [896]=shift2
__device__ float g_bn[8 * 128];

// ---------------- preprocessing ----------------
__global__ void zero_k() {
    int i = blockIdx.x * blockDim.x + threadIdx.x;
    if (i < NN) g_cursor[i] = 0;
    if (i < 8 * 128) g_bn[i] = 0.f;
}

// single atomic pass: scatter src into dst-bucketed list; cursor becomes in-degree
__global__ void fill_k(const int* __restrict__ src, const int* __restrict__ dst) {
    int i = blockIdx.x * blockDim.x + threadIdx.x;
    if (i < EE) {
        int s = src[i], d = dst[i];
        int pos = atomicAdd(&g_cursor[d], 1);
        if (pos < CAP) g_esrc[(size_t)d * CAP + pos] = s;
    }
}

__global__ void dinv_k() {
    int i = blockIdx.x * blockDim.x + threadIdx.x;
    if (i < NN) g_dinv[i] = rsqrtf((float)(g_cursor[i] + 1));  // +1 self loop
}

// ---------------- aggregation: one warp per node, lane owns 4 features ----------------
template<bool STATS, bool AFFINE, bool A2B>
__global__ void __launch_bounds__(256) agg_k(int bnoff, int affoff)
{
    const float* __restrict__ hin  = A2B ? g_bufA : g_bufB;
    float*       __restrict__ aout = A2B ? g_bufB : g_bufA;

    __shared__ float s_sum[128];
    __shared__ float s_sq[128];
    if (STATS) {
        if (threadIdx.x < 128) { s_sum[threadIdx.x] = 0.f; s_sq[threadIdx.x] = 0.f; }
        __syncthreads();
    }
    const int lane = threadIdx.x & 31;
    const int gw   = (blockIdx.x * blockDim.x + threadIdx.x) >> 5;
    const int nw   = (gridDim.x * blockDim.x) >> 5;
    const int f    = lane * 4;

    float sc0 = 0, sc1 = 0, sc2 = 0, sc3 = 0, sh0 = 0, sh1 = 0, sh2 = 0, sh3 = 0;
    if (AFFINE) {
        const float* scale = g_bn + affoff;
        const float* shift = g_bn + affoff + 128;
        sc0 = scale[f + 0]; sc1 = scale[f + 1]; sc2 = scale[f + 2]; sc3 = scale[f + 3];
        sh0 = shift[f + 0]; sh1 = shift[f + 1]; sh2 = shift[f + 2]; sh3 = shift[f + 3];
    }
    float t0 = 0, t1 = 0, t2 = 0, t3 = 0;
    float q0 = 0, q1 = 0, q2 = 0, q3 = 0;

    for (int node = gw; node < NN; node += nw) {
        int cnt = g_cursor[node];
        if (cnt > CAP) cnt = CAP;
        const float dd  = g_dinv[node];
        const size_t base = (size_t)node * CAP;

        float4 v = *(const float4*)&hin[(size_t)node * HID + f];
        if (AFFINE) {
            v.x = fmaxf(fmaf(v.x, sc0, sh0), 0.f);
            v.y = fmaxf(fmaf(v.y, sc1, sh1), 0.f);
            v.z = fmaxf(fmaf(v.z, sc2, sh2), 0.f);
            v.w = fmaxf(fmaf(v.w, sc3, sh3), 0.f);
        }
        float px = dd * v.x, py = dd * v.y, pz = dd * v.z, pw = dd * v.w;

        int e = 0;
        for (; e + 4 <= cnt; e += 4) {
            int   s0 = g_esrc[base + e + 0], s1 = g_esrc[base + e + 1];
            int   s2 = g_esrc[base + e + 2], s3 = g_esrc[base + e + 3];
            float n0 = g_dinv[s0], n1 = g_dinv[s1], n2 = g_dinv[s2], n3 = g_dinv[s3];
            float4 u0 = *(const float4*)&hin[(size_t)s0 * HID + f];
            float4 u1 = *(const float4*)&hin[(size_t)s1 * HID + f];
            float4 u2 = *(const float4*)&hin[(size_t)s2 * HID + f];
            float4 u3 = *(const float4*)&hin[(size_t)s3 * HID + f];
            if (AFFINE) {
                u0.x = fmaxf(fmaf(u0.x, sc0, sh0), 0.f); u0.y = fmaxf(fmaf(u0.y, sc1, sh1), 0.f);
                u0.z = fmaxf(fmaf(u0.z, sc2, sh2), 0.f); u0.w = fmaxf(fmaf(u0.w, sc3, sh3), 0.f);
                u1.x = fmaxf(fmaf(u1.x, sc0, sh0), 0.f); u1.y = fmaxf(fmaf(u1.y, sc1, sh1), 0.f);
                u1.z = fmaxf(fmaf(u1.z, sc2, sh2), 0.f); u1.w = fmaxf(fmaf(u1.w, sc3, sh3), 0.f);
                u2.x = fmaxf(fmaf(u2.x, sc0, sh0), 0.f); u2.y = fmaxf(fmaf(u2.y, sc1, sh1), 0.f);
                u2.z = fmaxf(fmaf(u2.z, sc2, sh2), 0.f); u2.w = fmaxf(fmaf(u2.w, sc3, sh3), 0.f);
                u3.x = fmaxf(fmaf(u3.x, sc0, sh0), 0.f); u3.y = fmaxf(fmaf(u3.y, sc1, sh1), 0.f);
                u3.z = fmaxf(fmaf(u3.z, sc2, sh2), 0.f); u3.w = fmaxf(fmaf(u3.w, sc3, sh3), 0.f);
            }
            px = fmaf(n0, u0.x, px); py = fmaf(n0, u0.y, py); pz = fmaf(n0, u0.z, pz); pw = fmaf(n0, u0.w, pw);
            px = fmaf(n1, u1.x, px); py = fmaf(n1, u1.y, py); pz = fmaf(n1, u1.z, pz); pw = fmaf(n1, u1.w, pw);
            px = fmaf(n2, u2.x, px); py = fmaf(n2, u2.y, py); pz = fmaf(n2, u2.z, pz); pw = fmaf(n2, u2.w, pw);
            px = fmaf(n3, u3.x, px); py = fmaf(n3, u3.y, py); pz = fmaf(n3, u3.z, pz); pw = fmaf(n3, u3.w, pw);
        }
        for (; e < cnt; e++) {
            int   s  = g_esrc[base + e];
            float nn = g_dinv[s];
            float4 u = *(const float4*)&hin[(size_t)s * HID + f];
            if (AFFINE) {
                u.x = fmaxf(fmaf(u.x, sc0, sh0), 0.f); u.y = fmaxf(fmaf(u.y, sc1, sh1), 0.f);
                u.z = fmaxf(fmaf(u.z, sc2, sh2), 0.f); u.w = fmaxf(fmaf(u.w, sc3, sh3), 0.f);
            }
            px = fmaf(nn, u.x, px); py = fmaf(nn, u.y, py);
            pz = fmaf(nn, u.z, pz); pw = fmaf(nn, u.w, pw);
        }

        float ax = dd * px, ay = dd * py, az = dd * pz, aw = dd * pw;
        *(float4*)&aout[(size_t)node * HID + f] = make_float4(ax, ay, az, aw);
        if (STATS) {
            t0 += ax; t1 += ay; t2 += az; t3 += aw;
            q0 += ax * ax; q1 += ay * ay; q2 += az * az; q3 += aw * aw;
        }
    }

    if (STATS) {
        atomicAdd(&s_sum[f + 0], t0); atomicAdd(&s_sum[f + 1], t1);
        atomicAdd(&s_sum[f + 2], t2); atomicAdd(&s_sum[f + 3], t3);
        atomicAdd(&s_sq[f + 0], q0);  atomicAdd(&s_sq[f + 1], q1);
        atomicAdd(&s_sq[f + 2], q2);  atomicAdd(&s_sq[f + 3], q3);
        __syncthreads();
        if (threadIdx.x < 128) {
            atomicAdd(&g_bn[bnoff + threadIdx.x],       s_sum[threadIdx.x]);
            atomicAdd(&g_bn[bnoff + 128 + threadIdx.x], s_sq [threadIdx.x]);
        }
    }
}

// ---------------- BN finalize ----------------
__global__ void bnfin_k(int statoff, int outoff,
                        const float* __restrict__ g, const float* __restrict__ bt)
{
    int t = threadIdx.x;
    if (t < 128) {
        float m  = g_bn[statoff + t] * (1.f / NN);
        float v  = fmaxf(g_bn[statoff + 128 + t] * (1.f / NN) - m * m, 0.f);
        float sc = g[t] * rsqrtf(v + EPSB);
        g_bn[outoff + t]       = sc;
        g_bn[outoff + 128 + t] = bt[t] - m * sc;
    }
}

// ---------------- bf16-split tensor-core GEMM, register-prefetch pipelined ----------------
// C[N,128] = f(A[N,K]) @ B[K,128] ~= AhBh + AlBh + AhBl
// Block 128x128, BK=32, 256 threads = 8 warps (2M x 4N), warp tile 64x32, mma m16n8k16.
// Pipeline: while computing tile k, global loads for tile k+1 sit in registers.
#define SA  40      // A smem k-stride (bf16 elems)
#define SBN 136     // B smem n-stride (bf16 elems), row k-major

__device__ __forceinline__ void mma_bf16(float* c, const uint32_t* a, const uint32_t* b) {
    asm volatile("mma.sync.aligned.m16n8k16.row.col.f32.bf16.bf16.f32 "
        "{%0,%1,%2,%3}, {%4,%5,%6,%7}, {%8,%9}, {%0,%1,%2,%3};"
        : "+f"(c[0]), "+f"(c[1]), "+f"(c[2]), "+f"(c[3])
        : "r"(a[0]), "r"(a[1]), "r"(a[2]), "r"(a[3]), "r"(b[0]), "r"(b[1]));
}
__device__ __forceinline__ void ldmx2t(uint32_t &r0, uint32_t &r1, const __nv_bfloat16* p) {
    uint32_t addr = (uint32_t)__cvta_generic_to_shared(p);
    asm volatile("ldmatrix.sync.aligned.m8n8.x2.trans.shared.b16 {%0,%1}, [%2];"
        : "=r"(r0), "=r"(r1) : "r"(addr));
}
__device__ __forceinline__ uint32_t packbf2(float a, float b) {
    uint32_t ha = (uint32_t)__bfloat16_as_ushort(__float2bfloat16(a));
    uint32_t hb = (uint32_t)__bfloat16_as_ushort(__float2bfloat16(b));
    return ha | (hb << 16);
}

template<bool AFFINE, bool SPLIT, int ASRC>
__global__ void __launch_bounds__(256) gemm_k(
    const float* __restrict__ Aext, int K,
    const float* __restrict__ B0, const float* __restrict__ B1,
    const float* __restrict__ bias0, const float* __restrict__ bias1,
    int affoff, float* __restrict__ Cext)
{
    const float* __restrict__ A = (ASRC == 0) ? Aext : (ASRC == 1 ? g_bufB : g_bufA);
    float* __restrict__ C = SPLIT ? Cext : g_bufA;

    __shared__ __align__(16) __nv_bfloat16 sAh[128 * SA], sAl[128 * SA];
    __shared__ __align__(16) __nv_bfloat16 sBh[32 * SBN], sBl[32 * SBN];
    __shared__ float ssc[128], ssh[128];

    const int t    = threadIdx.x;
    const int lane = t & 31;
    const int warp = t >> 5;
    const int wm   = warp >> 2;         // 0..1
    const int wn   = warp & 3;          // 0..3
    const int lr   = lane >> 2;         // 0..7
    const int lc   = (lane & 3) * 2;    // 0,2,4,6
    const int r0   = blockIdx.x * 128;

    if (AFFINE) {
        if (t < 128) { ssc[t] = g_bn[affoff + t]; ssh[t] = g_bn[affoff + 128 + t]; }
        __syncthreads();
    }

    // per-thread tile coordinates (fixed across iterations)
    const int a_row = t >> 1;              // with i*256 offset: rows (t+i*256)>>3
    (void)a_row;

    float pa[16], pb[16];

    // ---- prefetch helpers (inlined twice below) ----
    // A element map: v = t + i*256; row = v>>3; c4 = (v&7)*4
    // B element map: v = t + i*256; kr = v>>5; c4 = (v&31)*4

#define LOAD_TILES(kk)                                                          \
    {                                                                           \
        _Pragma("unroll")                                                       \
        for (int i = 0; i < 4; i++) {                                           \
            int v = t + i * 256, row = v >> 3, c4 = (v & 7) * 4;                \
            int gr = r0 + row;                                                  \
            float4 val = make_float4(0.f, 0.f, 0.f, 0.f);                       \
            if (gr < NN) val = *(const float4*)&A[(size_t)gr * K + (kk) + c4];  \
            pa[i*4+0] = val.x; pa[i*4+1] = val.y;                               \
            pa[i*4+2] = val.z; pa[i*4+3] = val.w;                               \
        }                                                                       \
        _Pragma("unroll")                                                       \
        for (int i = 0; i < 4; i++) {                                           \
            int v = t + i * 256, kr = v >> 5, c4 = (v & 31) * 4;                \
            float4 val;                                                         \
            if (!SPLIT) val = *(const float4*)&B0[(size_t)((kk) + kr) * 128 + c4]; \
            else        val = (c4 < 64) ? *(const float4*)&B0[(size_t)((kk) + kr) * 64 + c4] \
                                        : *(const float4*)&B1[(size_t)((kk) + kr) * 64 + c4 - 64]; \
            pb[i*4+0] = val.x; pb[i*4+1] = val.y;                               \
            pb[i*4+2] = val.z; pb[i*4+3] = val.w;                               \
        }                                                                       \
    }

#define STORE_TILES(kk)                                                         \
    {                                                                           \
        _Pragma("unroll")                                                       \
        for (int i = 0; i < 4; i++) {                                           \
            int v = t + i * 256, row = v >> 3, c4 = (v & 7) * 4;                \
            float f0 = pa[i*4+0], f1 = pa[i*4+1], f2 = pa[i*4+2], f3 = pa[i*4+3]; \
            if (AFFINE) {                                                       \
                f0 = fmaxf(fmaf(f0, ssc[(kk) + c4 + 0], ssh[(kk) + c4 + 0]), 0.f); \
                f1 = fmaxf(fmaf(f1, ssc[(kk) + c4 + 1], ssh[(kk) + c4 + 1]), 0.f); \
                f2 = fmaxf(fmaf(f2, ssc[(kk) + c4 + 2], ssh[(kk) + c4 + 2]), 0.f); \
                f3 = fmaxf(fmaf(f3, ssc[(kk) + c4 + 3], ssh[(kk) + c4 + 3]), 0.f); \
            }                                                                   \
            float h0 = __bfloat162float(__float2bfloat16(f0));                  \
            float h1 = __bfloat162float(__float2bfloat16(f1));                  \
            float h2 = __bfloat162float(__float2bfloat16(f2));                  \
            float h3 = __bfloat162float(__float2bfloat16(f3));                  \
            int o = row * SA + c4;                                              \
            *(uint32_t*)&sAh[o]     = packbf2(h0, h1);                          \
            *(uint32_t*)&sAh[o + 2] = packbf2(h2, h3);                          \
            *(uint32_t*)&sAl[o]     = packbf2(f0 - h0, f1 - h1);                \
            *(uint32_t*)&sAl[o + 2] = packbf2(f2 - h2, f3 - h3);                \
        }                                                                       \
        _Pragma("unroll")                                                       \
        for (int i = 0; i < 4; i++) {                                           \
            int v = t + i * 256, kr = v >> 5, c4 = (v & 31) * 4;                \
            float f0 = pb[i*4+0], f1 = pb[i*4+1], f2 = pb[i*4+2], f3 = pb[i*4+3]; \
            float h0 = __bfloat162float(__float2bfloat16(f0));                  \
            float h1 = __bfloat162float(__float2bfloat16(f1));                  \
            float h2 = __bfloat162float(__float2bfloat16(f2));                  \
            float h3 = __bfloat162float(__float2bfloat16(f3));                  \
            int o = kr * SBN + c4;                                              \
            *(uint32_t*)&sBh[o]     = packbf2(h0, h1);                          \
            *(uint32_t*)&sBh[o + 2] = packbf2(h2, h3);                          \
            *(uint32_t*)&sBl[o]     = packbf2(f0 - h0, f1 - h1);                \
            *(uint32_t*)&sBl[o + 2] = packbf2(f2 - h2, f3 - h3);                \
        }                                                                       \
    }

    float acc[4][4][4];
    #pragma unroll
    for (int mt = 0; mt < 4; mt++)
        #pragma unroll
        for (int nt = 0; nt < 4; nt++)
            #pragma unroll
            for (int j = 0; j < 4; j++) acc[mt][nt][j] = 0.f;

    // prologue: tile 0
    LOAD_TILES(0)
    STORE_TILES(0)
    __syncthreads();

    for (int kk = 0; kk < K; kk += 32) {
        const bool more = (kk + 32 < K);
        if (more) LOAD_TILES(kk + 32)     // LDGs in flight during MMA below

        #pragma unroll
        for (int ks = 0; ks < 32; ks += 16) {
            uint32_t aH[4][4], aL[4][4];
            #pragma unroll
            for (int mt = 0; mt < 4; mt++) {
                int r = wm * 64 + mt * 16 + lr;
                int o = r * SA + ks + lc;
                aH[mt][0] = *(const uint32_t*)&sAh[o];
                aH[mt][1] = *(const uint32_t*)&sAh[o + 8 * SA];
                aH[mt][2] = *(const uint32_t*)&sAh[o + 8];
                aH[mt][3] = *(const uint32_t*)&sAh[o + 8 * SA + 8];
                aL[mt][0] = *(const uint32_t*)&sAl[o];
                aL[mt][1] = *(const uint32_t*)&sAl[o + 8 * SA];
                aL[mt][2] = *(const uint32_t*)&sAl[o + 8];
                aL[mt][3] = *(const uint32_t*)&sAl[o + 8 * SA + 8];
            }
            uint32_t bb[4][2];
            #pragma unroll
            for (int nt = 0; nt < 4; nt++)
                ldmx2t(bb[nt][0], bb[nt][1],
                       &sBh[(ks + (lane & 15)) * SBN + wn * 32 + nt * 8]);
            #pragma unroll
            for (int mt = 0; mt < 4; mt++)
                #pragma unroll
                for (int nt = 0; nt < 4; nt++) mma_bf16(acc[mt][nt], aH[mt], bb[nt]); // HH
            #pragma unroll
            for (int mt = 0; mt < 4; mt++)
                #pragma unroll
                for (int nt = 0; nt < 4; nt++) mma_bf16(acc[mt][nt], aL[mt], bb[nt]); // LH
            #pragma unroll
            for (int nt = 0; nt < 4; nt++)
                ldmx2t(bb[nt][0], bb[nt][1],
                       &sBl[(ks + (lane & 15)) * SBN + wn * 32 + nt * 8]);
            #pragma unroll
            for (int mt = 0; mt < 4; mt++)
                #pragma unroll
                for (int nt = 0; nt < 4; nt++) mma_bf16(acc[mt][nt], aH[mt], bb[nt]); // HL
        }
        __syncthreads();
        if (more) {
            STORE_TILES(kk + 32)
            __syncthreads();
        }
    }

    // --- epilogue ---
    #pragma unroll
    for (int mt = 0; mt < 4; mt++) {
        int r = r0 + wm * 64 + mt * 16 + lr;
        #pragma unroll
        for (int nt = 0; nt < 4; nt++) {
            int col = wn * 32 + nt * 8 + lc;
            float* a4 = acc[mt][nt];
            if (!SPLIT) {
                if (r < NN)     *(float2*)&C[(size_t)r * 128 + col]       = make_float2(a4[0], a4[1]);
                if (r + 8 < NN) *(float2*)&C[(size_t)(r + 8) * 128 + col] = make_float2(a4[2], a4[3]);
            } else {
                int half = col >> 6;
                int c    = col & 63;
                const float* bs = half ? bias1 : bias0;
                size_t ofs = half ? (size_t)NN * 64 : 0;
                float b0v = bs[c], b1v = bs[c + 1];
                if (r < NN)
                    *(float2*)&C[ofs + (size_t)r * 64 + c] = make_float2(a4[0] + b0v, a4[1] + b1v);
                if (r + 8 < NN)
                    *(float2*)&C[ofs + (size_t)(r + 8) * 64 + c] = make_float2(a4[2] + b0v, a4[3] + b1v);
            }
        }
    }
#undef LOAD_TILES
#undef STORE_TILES
}

// ---------------- launch: pure kernel launches ----------------
extern "C" void kernel_launch(void* const* d_in, const int* in_sizes, int n_in,
                              void* d_out, int out_size)
{
    const float* x   = (const float*)d_in[0];
    const float* W1  = (const float*)d_in[1];
    // d_in[2] = b1 (cancels through BN), d_in[6] = b2 (cancels)
    const float* g1  = (const float*)d_in[3];
    const float* bt1 = (const float*)d_in[4];
    const float* W2  = (const float*)d_in[5];
    const float* g2  = (const float*)d_in[7];
    const float* bt2 = (const float*)d_in[8];
    const float* Wmu = (const float*)d_in[9];
    const float* bmu = (const float*)d_in[10];
    const float* Wls = (const float*)d_in[11];
    const float* bls = (const float*)d_in[12];
    const int*   ei  = (const int*)d_in[13];
    const int* esrc = ei;          // edge_index[0]
    const int* edst = ei + EE;     // edge_index[1]
    float* out = (float*)d_out;

    const int TB = 256;
    zero_k<<<(NN + TB - 1) / TB, TB>>>();
    fill_k<<<(EE + TB - 1) / TB, TB>>>(esrc, edst);
    dinv_k<<<(NN + TB - 1) / TB, TB>>>();

    const int GB = (NN + 127) / 128;   // 782
    const int AGG_BLOCKS = 1480;

    // layer 1: bufA = x@W1 ; bufB = Agg(bufA) (+stats@0) ; BN1 params -> g_bn[256..511]
    gemm_k<false, false, 0><<<GB, TB>>>(x, 256, W1, nullptr, nullptr, nullptr, 0, nullptr);
    agg_k<true, false, true><<<AGG_BLOCKS, TB>>>(0, 0);
    bnfin_k<<<1, 128>>>(0, 256, g1, bt1);

    // layer 2: bufA = relu(BN1(bufB))@W2 (affine fused) ; bufB = Agg(bufA) (+stats@512) ; BN2 -> g_bn[768..1023]
    gemm_k<true, false, 1><<<GB, TB>>>(nullptr, 128, W2, nullptr, nullptr, nullptr, 256, nullptr);
    agg_k<true, false, true><<<AGG_BLOCKS, TB>>>(512, 0);
    bnfin_k<<<1, 128>>>(512, 768, g2, bt2);

    // heads: bufA = Agg(relu(BN2(bufB))) ; out = bufA@[Wmu|Wls] + bias
    agg_k<false, true, false><<<AGG_BLOCKS, TB>>>(0, 768);
    gemm_k<false, true, 2><<<GB, TB>>>(nullptr, 128, Wmu, Wls, bmu, bls, 0, out);
}

// round 8
// speedup vs baseline: 1.1407x; 1.1407x over previous
#include <cuda_runtime.h>
#include <cuda_bf16.h>
#include <math.h>
#include <stdint.h>

#define NN  100000
#define EE  1600000
#define HID 128
#define CAP 128
#define EPSB 1e-5f

// ---------------- scratch (static device globals; no allocation anywhere) ----------------
__device__ int   g_cursor[NN];                 // doubles as in-degree count
__device__ float g_dinv[NN];
__device__ int   g_esrc [(size_t)NN * CAP];
__device__ float g_bufA[(size_t)NN * HID];
__device__ float g_bufB[(size_t)NN * HID];
// layout: [0]=sum1 [128]=sq1 [256]=scale1 [384]=shift1 [512]=sum2 [640]=sq2 [768]=scale2 [896]=shift2
__device__ float g_bn[8 * 128];

// ---------------- preprocessing ----------------
__global__ void zero_k() {
    int i = blockIdx.x * blockDim.x + threadIdx.x;
    if (i < NN) g_cursor[i] = 0;
    if (i < 8 * 128) g_bn[i] = 0.f;
}

__global__ void fill_k(const int* __restrict__ src, const int* __restrict__ dst) {
    int i = blockIdx.x * blockDim.x + threadIdx.x;
    if (i < EE) {
        int s = src[i], d = dst[i];
        int pos = atomicAdd(&g_cursor[d], 1);
        if (pos < CAP) g_esrc[(size_t)d * CAP + pos] = s;
    }
}

__global__ void dinv_k() {
    int i = blockIdx.x * blockDim.x + threadIdx.x;
    if (i < NN) g_dinv[i] = rsqrtf((float)(g_cursor[i] + 1));  // +1 self loop
}

// ---------------- aggregation: one warp per node, lane owns 4 features ----------------
template<bool STATS, bool AFFINE, bool A2B>
__global__ void __launch_bounds__(256) agg_k(int bnoff, int affoff)
{
    const float* __restrict__ hin  = A2B ? g_bufA : g_bufB;
    float*       __restrict__ aout = A2B ? g_bufB : g_bufA;

    __shared__ float s_sum[128];
    __shared__ float s_sq[128];
    if (STATS) {
        if (threadIdx.x < 128) { s_sum[threadIdx.x] = 0.f; s_sq[threadIdx.x] = 0.f; }
        __syncthreads();
    }
    const int lane = threadIdx.x & 31;
    const int gw   = (blockIdx.x * blockDim.x + threadIdx.x) >> 5;
    const int nw   = (gridDim.x * blockDim.x) >> 5;
    const int f    = lane * 4;

    float sc0 = 0, sc1 = 0, sc2 = 0, sc3 = 0, sh0 = 0, sh1 = 0, sh2 = 0, sh3 = 0;
    if (AFFINE) {
        const float* scale = g_bn + affoff;
        const float* shift = g_bn + affoff + 128;
        sc0 = scale[f + 0]; sc1 = scale[f + 1]; sc2 = scale[f + 2]; sc3 = scale[f + 3];
        sh0 = shift[f + 0]; sh1 = shift[f + 1]; sh2 = shift[f + 2]; sh3 = shift[f + 3];
    }
    float t0 = 0, t1 = 0, t2 = 0, t3 = 0;
    float q0 = 0, q1 = 0, q2 = 0, q3 = 0;

    for (int node = gw; node < NN; node += nw) {
        int cnt = g_cursor[node];
        if (cnt > CAP) cnt = CAP;
        const float dd  = g_dinv[node];
        const size_t base = (size_t)node * CAP;

        float4 v = *(const float4*)&hin[(size_t)node * HID + f];
        if (AFFINE) {
            v.x = fmaxf(fmaf(v.x, sc0, sh0), 0.f);
            v.y = fmaxf(fmaf(v.y, sc1, sh1), 0.f);
            v.z = fmaxf(fmaf(v.z, sc2, sh2), 0.f);
            v.w = fmaxf(fmaf(v.w, sc3, sh3), 0.f);
        }
        float px = dd * v.x, py = dd * v.y, pz = dd * v.z, pw = dd * v.w;

        int e = 0;
        for (; e + 4 <= cnt; e += 4) {
            int   s0 = g_esrc[base + e + 0], s1 = g_esrc[base + e + 1];
            int   s2 = g_esrc[base + e + 2], s3 = g_esrc[base + e + 3];
            float n0 = g_dinv[s0], n1 = g_dinv[s1], n2 = g_dinv[s2], n3 = g_dinv[s3];
            float4 u0 = *(const float4*)&hin[(size_t)s0 * HID + f];
            float4 u1 = *(const float4*)&hin[(size_t)s1 * HID + f];
            float4 u2 = *(const float4*)&hin[(size_t)s2 * HID + f];
            float4 u3 = *(const float4*)&hin[(size_t)s3 * HID + f];
            if (AFFINE) {
                u0.x = fmaxf(fmaf(u0.x, sc0, sh0), 0.f); u0.y = fmaxf(fmaf(u0.y, sc1, sh1), 0.f);
                u0.z = fmaxf(fmaf(u0.z, sc2, sh2), 0.f); u0.w = fmaxf(fmaf(u0.w, sc3, sh3), 0.f);
                u1.x = fmaxf(fmaf(u1.x, sc0, sh0), 0.f); u1.y = fmaxf(fmaf(u1.y, sc1, sh1), 0.f);
                u1.z = fmaxf(fmaf(u1.z, sc2, sh2), 0.f); u1.w = fmaxf(fmaf(u1.w, sc3, sh3), 0.f);
                u2.x = fmaxf(fmaf(u2.x, sc0, sh0), 0.f); u2.y = fmaxf(fmaf(u2.y, sc1, sh1), 0.f);
                u2.z = fmaxf(fmaf(u2.z, sc2, sh2), 0.f); u2.w = fmaxf(fmaf(u2.w, sc3, sh3), 0.f);
                u3.x = fmaxf(fmaf(u3.x, sc0, sh0), 0.f); u3.y = fmaxf(fmaf(u3.y, sc1, sh1), 0.f);
                u3.z = fmaxf(fmaf(u3.z, sc2, sh2), 0.f); u3.w = fmaxf(fmaf(u3.w, sc3, sh3), 0.f);
            }
            px = fmaf(n0, u0.x, px); py = fmaf(n0, u0.y, py); pz = fmaf(n0, u0.z, pz); pw = fmaf(n0, u0.w, pw);
            px = fmaf(n1, u1.x, px); py = fmaf(n1, u1.y, py); pz = fmaf(n1, u1.z, pz); pw = fmaf(n1, u1.w, pw);
            px = fmaf(n2, u2.x, px); py = fmaf(n2, u2.y, py); pz = fmaf(n2, u2.z, pz); pw = fmaf(n2, u2.w, pw);
            px = fmaf(n3, u3.x, px); py = fmaf(n3, u3.y, py); pz = fmaf(n3, u3.z, pz); pw = fmaf(n3, u3.w, pw);
        }
        for (; e < cnt; e++) {
            int   s  = g_esrc[base + e];
            float nn = g_dinv[s];
            float4 u = *(const float4*)&hin[(size_t)s * HID + f];
            if (AFFINE) {
                u.x = fmaxf(fmaf(u.x, sc0, sh0), 0.f); u.y = fmaxf(fmaf(u.y, sc1, sh1), 0.f);
                u.z = fmaxf(fmaf(u.z, sc2, sh2), 0.f); u.w = fmaxf(fmaf(u.w, sc3, sh3), 0.f);
            }
            px = fmaf(nn, u.x, px); py = fmaf(nn, u.y, py);
            pz = fmaf(nn, u.z, pz); pw = fmaf(nn, u.w, pw);
        }

        float ax = dd * px, ay = dd * py, az = dd * pz, aw = dd * pw;
        *(float4*)&aout[(size_t)node * HID + f] = make_float4(ax, ay, az, aw);
        if (STATS) {
            t0 += ax; t1 += ay; t2 += az; t3 += aw;
            q0 += ax * ax; q1 += ay * ay; q2 += az * az; q3 += aw * aw;
        }
    }

    if (STATS) {
        atomicAdd(&s_sum[f + 0], t0); atomicAdd(&s_sum[f + 1], t1);
        atomicAdd(&s_sum[f + 2], t2); atomicAdd(&s_sum[f + 3], t3);
        atomicAdd(&s_sq[f + 0], q0);  atomicAdd(&s_sq[f + 1], q1);
        atomicAdd(&s_sq[f + 2], q2);  atomicAdd(&s_sq[f + 3], q3);
        __syncthreads();
        if (threadIdx.x < 128) {
            atomicAdd(&g_bn[bnoff + threadIdx.x],       s_sum[threadIdx.x]);
            atomicAdd(&g_bn[bnoff + 128 + threadIdx.x], s_sq [threadIdx.x]);
        }
    }
}

// ---------------- BN finalize ----------------
__global__ void bnfin_k(int statoff, int outoff,
                        const float* __restrict__ g, const float* __restrict__ bt)
{
    int t = threadIdx.x;
    if (t < 128) {
        float m  = g_bn[statoff + t] * (1.f / NN);
        float v  = fmaxf(g_bn[statoff + 128 + t] * (1.f / NN) - m * m, 0.f);
        float sc = g[t] * rsqrtf(v + EPSB);
        g_bn[outoff + t]       = sc;
        g_bn[outoff + 128 + t] = bt[t] - m * sc;
    }
}

// ---------------- bf16-split tensor-core GEMM, cp.async pipelined ----------------
// C[N,128] = f(A[N,K]) @ B[K,128] ~= AhBh + AlBh + AhBl
// Block 128x128, BK=32, 256 threads = 8 warps (2M x 4N), warp tile 64x32, mma m16n8k16.
// cp.async stages next fp32 tile into smem while MMAs run; zero regs live across MMA.
#define SA  40      // A smem k-stride (bf16 elems)
#define SBN 136     // B smem n-stride (bf16 elems), row k-major

// dynamic smem layout (bytes):
//   [0)      sAh 10240 | [10240) sAl 10240 | [20480) sBh 8704 | [29184) sBl 8704
//   [37888)  stA 16384 | [54272) stB 16384 | [70656) ssc 512  | [71168) ssh 512
#define GEMM_SMEM 71680

__device__ __forceinline__ void mma_bf16(float* c, const uint32_t* a, const uint32_t* b) {
    asm volatile("mma.sync.aligned.m16n8k16.row.col.f32.bf16.bf16.f32 "
        "{%0,%1,%2,%3}, {%4,%5,%6,%7}, {%8,%9}, {%0,%1,%2,%3};"
        : "+f"(c[0]), "+f"(c[1]), "+f"(c[2]), "+f"(c[3])
        : "r"(a[0]), "r"(a[1]), "r"(a[2]), "r"(a[3]), "r"(b[0]), "r"(b[1]));
}
__device__ __forceinline__ void ldmx2t(uint32_t &r0, uint32_t &r1, const __nv_bfloat16* p) {
    uint32_t addr = (uint32_t)__cvta_generic_to_shared(p);
    asm volatile("ldmatrix.sync.aligned.m8n8.x2.trans.shared.b16 {%0,%1}, [%2];"
        : "=r"(r0), "=r"(r1) : "r"(addr));
}
__device__ __forceinline__ uint32_t packbf2(float a, float b) {
    uint32_t ha = (uint32_t)__bfloat16_as_ushort(__float2bfloat16(a));
    uint32_t hb = (uint32_t)__bfloat16_as_ushort(__float2bfloat16(b));
    return ha | (hb << 16);
}
__device__ __forceinline__ void cp16(void* smem, const void* gmem, bool pred) {
    uint32_t s = (uint32_t)__cvta_generic_to_shared(smem);
    int sz = pred ? 16 : 0;   // src-size 0 => zero-fill 16B
    asm volatile("cp.async.cg.shared.global [%0], [%1], 16, %2;" :: "r"(s), "l"(gmem), "r"(sz));
}

template<bool AFFINE, bool SPLIT, int ASRC>
__global__ void __launch_bounds__(256, 2) gemm_k(
    const float* __restrict__ Aext, int K,
    const float* __restrict__ B0, const float* __restrict__ B1,
    const float* __restrict__ bias0, const float* __restrict__ bias1,
    int affoff, float* __restrict__ Cext)
{
    const float* __restrict__ A = (ASRC == 0) ? Aext : (ASRC == 1 ? g_bufB : g_bufA);
    float* __restrict__ C = SPLIT ? Cext : g_bufA;

    extern __shared__ __align__(16) char dsm[];
    __nv_bfloat16* sAh = (__nv_bfloat16*)dsm;
    __nv_bfloat16* sAl = (__nv_bfloat16*)(dsm + 10240);
    __nv_bfloat16* sBh = (__nv_bfloat16*)(dsm + 20480);
    __nv_bfloat16* sBl = (__nv_bfloat16*)(dsm + 29184);
    float*         stA = (float*)(dsm + 37888);
    float*         stB = (float*)(dsm + 54272);
    float*         ssc = (float*)(dsm + 70656);
    float*         ssh = (float*)(dsm + 71168);

    const int t    = threadIdx.x;
    const int lane = t & 31;
    const int warp = t >> 5;
    const int wm   = warp >> 2;         // 0..1
    const int wn   = warp & 3;          // 0..3
    const int lr   = lane >> 2;         // 0..7
    const int lc   = (lane & 3) * 2;    // 0,2,4,6
    const int r0   = blockIdx.x * 128;

    if (AFFINE) {
        if (t < 128) { ssc[t] = g_bn[affoff + t]; ssh[t] = g_bn[affoff + 128 + t]; }
        __syncthreads();
    }

// issue cp.async for tile at k-offset (kk): A 128x32, B 32x128 fp32 into staging
#define ISSUE_TILES(kk)                                                         \
    {                                                                           \
        _Pragma("unroll")                                                       \
        for (int i = 0; i < 4; i++) {                                           \
            int v = t + i * 256, row = v >> 3, c4 = (v & 7) * 4;                \
            int gr = r0 + row;                                                  \
            bool ok = gr < NN;                                                  \
            const float* gp = &A[(size_t)(ok ? gr : 0) * K + (kk) + c4];        \
            cp16(&stA[row * 32 + c4], gp, ok);                                  \
        }                                                                       \
        _Pragma("unroll")                                                       \
        for (int i = 0; i < 4; i++) {                                           \
            int v = t + i * 256, kr = v >> 5, c4 = (v & 31) * 4;                \
            const float* gp;                                                    \
            if (!SPLIT) gp = &B0[(size_t)((kk) + kr) * 128 + c4];               \
            else        gp = (c4 < 64) ? &B0[(size_t)((kk) + kr) * 64 + c4]     \
                                       : &B1[(size_t)((kk) + kr) * 64 + c4 - 64]; \
            cp16(&stB[kr * 128 + c4], gp, true);                                \
        }                                                                       \
        asm volatile("cp.async.commit_group;");                                 \
    }

// convert staged fp32 tile -> bf16 hi/lo split smem
#define CONVERT_TILES(kk)                                                       \
    {                                                                           \
        _Pragma("unroll")                                                       \
        for (int i = 0; i < 4; i++) {                                           \
            int v = t + i * 256, row = v >> 3, c4 = (v & 7) * 4;                \
            float4 val = *(const float4*)&stA[row * 32 + c4];                   \
            float f0 = val.x, f1 = val.y, f2 = val.z, f3 = val.w;               \
            if (AFFINE) {                                                       \
                f0 = fmaxf(fmaf(f0, ssc[(kk) + c4 + 0], ssh[(kk) + c4 + 0]), 0.f); \
                f1 = fmaxf(fmaf(f1, ssc[(kk) + c4 + 1], ssh[(kk) + c4 + 1]), 0.f); \
                f2 = fmaxf(fmaf(f2, ssc[(kk) + c4 + 2], ssh[(kk) + c4 + 2]), 0.f); \
                f3 = fmaxf(fmaf(f3, ssc[(kk) + c4 + 3], ssh[(kk) + c4 + 3]), 0.f); \
            }                                                                   \
            float h0 = __bfloat162float(__float2bfloat16(f0));                  \
            float h1 = __bfloat162float(__float2bfloat16(f1));                  \
            float h2 = __bfloat162float(__float2bfloat16(f2));                  \
            float h3 = __bfloat162float(__float2bfloat16(f3));                  \
            int o = row * SA + c4;                                              \
            *(uint32_t*)&sAh[o]     = packbf2(h0, h1);                          \
            *(uint32_t*)&sAh[o + 2] = packbf2(h2, h3);                          \
            *(uint32_t*)&sAl[o]     = packbf2(f0 - h0, f1 - h1);                \
            *(uint32_t*)&sAl[o + 2] = packbf2(f2 - h2, f3 - h3);                \
        }                                                                       \
        _Pragma("unroll")                                                       \
        for (int i = 0; i < 4; i++) {                                           \
            int v = t + i * 256, kr = v >> 5, c4 = (v & 31) * 4;                \
            float4 val = *(const float4*)&stB[kr * 128 + c4];                   \
            float f0 = val.x, f1 = val.y, f2 = val.z, f3 = val.w;               \
            float h0 = __bfloat162float(__float2bfloat16(f0));                  \
            float h1 = __bfloat162float(__float2bfloat16(f1));                  \
            float h2 = __bfloat162float(__float2bfloat16(f2));                  \
            float h3 = __bfloat162float(__float2bfloat16(f3));                  \
            int o = kr * SBN + c4;                                              \
            *(uint32_t*)&sBh[o]     = packbf2(h0, h1);                          \
            *(uint32_t*)&sBh[o + 2] = packbf2(h2, h3);                          \
            *(uint32_t*)&sBl[o]     = packbf2(f0 - h0, f1 - h1);                \
            *(uint32_t*)&sBl[o + 2] = packbf2(f2 - h2, f3 - h3);                \
        }                                                                       \
    }

    float acc[4][4][4];
    #pragma unroll
    for (int mt = 0; mt < 4; mt++)
        #pragma unroll
        for (int nt = 0; nt < 4; nt++)
            #pragma unroll
            for (int j = 0; j < 4; j++) acc[mt][nt][j] = 0.f;

    ISSUE_TILES(0)

    for (int kk = 0; kk < K; kk += 32) {
        asm volatile("cp.async.wait_group 0;");
        __syncthreads();                 // stage(kk) complete; prior MMA smem reads done
        CONVERT_TILES(kk)
        __syncthreads();                 // split ready; stage free for overwrite
        if (kk + 32 < K) ISSUE_TILES(kk + 32)   // overlaps with MMA below

        #pragma unroll
        for (int ks = 0; ks < 32; ks += 16) {
            uint32_t aH[4][4], aL[4][4];
            #pragma unroll
            for (int mt = 0; mt < 4; mt++) {
                int r = wm * 64 + mt * 16 + lr;
                int o = r * SA + ks + lc;
                aH[mt][0] = *(const uint32_t*)&sAh[o];
                aH[mt][1] = *(const uint32_t*)&sAh[o + 8 * SA];
                aH[mt][2] = *(const uint32_t*)&sAh[o + 8];
                aH[mt][3] = *(const uint32_t*)&sAh[o + 8 * SA + 8];
                aL[mt][0] = *(const uint32_t*)&sAl[o];
                aL[mt][1] = *(const uint32_t*)&sAl[o + 8 * SA];
                aL[mt][2] = *(const uint32_t*)&sAl[o + 8];
                aL[mt][3] = *(const uint32_t*)&sAl[o + 8 * SA + 8];
            }
            uint32_t bb[4][2];
            #pragma unroll
            for (int nt = 0; nt < 4; nt++)
                ldmx2t(bb[nt][0], bb[nt][1],
                       &sBh[(ks + (lane & 15)) * SBN + wn * 32 + nt * 8]);
            #pragma unroll
            for (int mt = 0; mt < 4; mt++)
                #pragma unroll
                for (int nt = 0; nt < 4; nt++) mma_bf16(acc[mt][nt], aH[mt], bb[nt]); // HH
            #pragma unroll
            for (int mt = 0; mt < 4; mt++)
                #pragma unroll
                for (int nt = 0; nt < 4; nt++) mma_bf16(acc[mt][nt], aL[mt], bb[nt]); // LH
            #pragma unroll
            for (int nt = 0; nt < 4; nt++)
                ldmx2t(bb[nt][0], bb[nt][1],
                       &sBl[(ks + (lane & 15)) * SBN + wn * 32 + nt * 8]);
            #pragma unroll
            for (int mt = 0; mt < 4; mt++)
                #pragma unroll
                for (int nt = 0; nt < 4; nt++) mma_bf16(acc[mt][nt], aH[mt], bb[nt]); // HL
        }
    }

    // --- epilogue (reads only registers) ---
    #pragma unroll
    for (int mt = 0; mt < 4; mt++) {
        int r = r0 + wm * 64 + mt * 16 + lr;
        #pragma unroll
        for (int nt = 0; nt < 4; nt++) {
            int col = wn * 32 + nt * 8 + lc;
            float* a4 = acc[mt][nt];
            if (!SPLIT) {
                if (r < NN)     *(float2*)&C[(size_t)r * 128 + col]       = make_float2(a4[0], a4[1]);
                if (r + 8 < NN) *(float2*)&C[(size_t)(r + 8) * 128 + col] = make_float2(a4[2], a4[3]);
            } else {
                int half = col >> 6;
                int c    = col & 63;
                const float* bs = half ? bias1 : bias0;
                size_t ofs = half ? (size_t)NN * 64 : 0;
                float b0v = bs[c], b1v = bs[c + 1];
                if (r < NN)
                    *(float2*)&C[ofs + (size_t)r * 64 + c] = make_float2(a4[0] + b0v, a4[1] + b1v);
                if (r + 8 < NN)
                    *(float2*)&C[ofs + (size_t)(r + 8) * 64 + c] = make_float2(a4[2] + b0v, a4[3] + b1v);
            }
        }
    }
#undef ISSUE_TILES
#undef CONVERT_TILES
}

// ---------------- launch: kernel launches + one capture-safe attribute opt-in ----------------
extern "C" void kernel_launch(void* const* d_in, const int* in_sizes, int n_in,
                              void* d_out, int out_size)
{
    const float* x   = (const float*)d_in[0];
    const float* W1  = (const float*)d_in[1];
    // d_in[2] = b1 (cancels through BN), d_in[6] = b2 (cancels)
    const float* g1  = (const float*)d_in[3];
    const float* bt1 = (const float*)d_in[4];
    const float* W2  = (const float*)d_in[5];
    const float* g2  = (const float*)d_in[7];
    const float* bt2 = (const float*)d_in[8];
    const float* Wmu = (const float*)d_in[9];
    const float* bmu = (const float*)d_in[10];
    const float* Wls = (const float*)d_in[11];
    const float* bls = (const float*)d_in[12];
    const int*   ei  = (const int*)d_in[13];
    const int* esrc = ei;          // edge_index[0]
    const int* edst = ei + EE;     // edge_index[1]
    float* out = (float*)d_out;

    // opt-in to >48KB dynamic smem (metadata only; no alloc, no stream op)
    cudaFuncSetAttribute(gemm_k<false, false, 0>, cudaFuncAttributeMaxDynamicSharedMemorySize, GEMM_SMEM);
    cudaFuncSetAttribute(gemm_k<true,  false, 1>, cudaFuncAttributeMaxDynamicSharedMemorySize, GEMM_SMEM);
    cudaFuncSetAttribute(gemm_k<false, true,  2>, cudaFuncAttributeMaxDynamicSharedMemorySize, GEMM_SMEM);

    const int TB = 256;
    zero_k<<<(NN + TB - 1) / TB, TB>>>();
    fill_k<<<(EE + TB - 1) / TB, TB>>>(esrc, edst);
    dinv_k<<<(NN + TB - 1) / TB, TB>>>();

    const int GB = (NN + 127) / 128;   // 782
    const int AGG_BLOCKS = 1480;

    // layer 1: bufA = x@W1 ; bufB = Agg(bufA) (+stats@0) ; BN1 params -> g_bn[256..511]
    gemm_k<false, false, 0><<<GB, TB, GEMM_SMEM>>>(x, 256, W1, nullptr, nullptr, nullptr, 0, nullptr);
    agg_k<true, false, true><<<AGG_BLOCKS, TB>>>(0, 0);
    bnfin_k<<<1, 128>>>(0, 256, g1, bt1);

    // layer 2: bufA = relu(BN1(bufB))@W2 (affine fused) ; bufB = Agg(bufA) (+stats@512) ; BN2 -> g_bn[768..1023]
    gemm_k<true, false, 1><<<GB, TB, GEMM_SMEM>>>(nullptr, 128, W2, nullptr, nullptr, nullptr, 256, nullptr);
    agg_k<true, false, true><<<AGG_BLOCKS, TB>>>(512, 0);
    bnfin_k<<<1, 128>>>(512, 768, g2, bt2);

    // heads: bufA = Agg(relu(BN2(bufB))) ; out = bufA@[Wmu|Wls] + bias
    agg_k<false, true, false><<<AGG_BLOCKS, TB>>>(0, 768);
    gemm_k<false, true, 2><<<GB, TB, GEMM_SMEM>>>(nullptr, 128, Wmu, Wls, bmu, bls, 0, out);
}